// round 4
// baseline (speedup 1.0000x reference)
#include <cuda_runtime.h>
#include <cstdint>

// HyenaSE gated causal depthwise conv, bdl layout.
// y[b,d,l] = q * sum_{s=0}^{127} (k*x)[b,d,l-s] * h[d%256][127-s]
//
// R4: L tiled into 2048-length segments (halo 128) and TPT cut 16->8 so 4
// blocks (32 warps) fit per SM -- overlaps one block's LDG prologue/epilogue
// with another block's FMA mainloop (R3 showed phase serialization at occ=2
// blocks: dur tracked 537MB/2.3TB/s, not the FMA floor).
// Channel pair (d, d+2048) shares filter group; kx interleaved in float2
// shared buffer; mainloop = packed fma.rn.f32x2. Padding every 16 float2
// keeps LDS.64 at the inherent 2-way conflict.

typedef unsigned long long u64;

#define B_  2
#define D_  4096
#define L_  4096
#define G_  256
#define HL_ 128
#define LT_ 2048                            // L tile per block

static constexpr int THREADS = 256;
static constexpr int TPT = 8;               // outputs per thread (LT_/THREADS)
static constexpr int U   = 8;               // taps per chunk
static constexpr int N2  = LT_ + HL_;       // 2176 float2 (128 halo + 2048)
static constexpr int NV4 = N2 / 4;          // 544 float4 rows per stream
__device__ __forceinline__ int padidx(int r) { return r + (r >> 4); }
static constexpr int NPAD = N2 + ((N2 - 1) >> 4) + 1;  // 2312

__device__ __forceinline__ void ffma2(u64& acc, u64 a, u64 b) {
    asm("fma.rn.f32x2 %0, %1, %2, %0;" : "+l"(acc) : "l"(a), "l"(b));
}

__global__ void __launch_bounds__(THREADS, 4)
hyena_se_kernel(const float* __restrict__ x, const float* __restrict__ k,
                const float* __restrict__ q, const float* __restrict__ h,
                float* __restrict__ out)
{
    __shared__ u64 sh[NPAD];   // interleaved kx pairs, padded
    __shared__ u64 w2[HL_];    // reversed filter, duplicated into both lanes

    const int tid = threadIdx.x;
    const int L0  = blockIdx.x * LT_;          // tile start along L
    const int dp  = blockIdx.y;                // channel in [0,2048)
    const int b   = blockIdx.z;
    const long row0 = (long)(b * D_ + dp) * L_;
    const long row1 = (long)(b * D_ + dp + 2048) * L_;
    const int g = dp & (G_ - 1);

    // Reversed filter: wrev[s] = h[g][HL-1-s], packed {w,w}
    for (int s = tid; s < HL_; s += THREADS) {
        unsigned wb = __float_as_uint(h[g * HL_ + (HL_ - 1 - s)]);
        w2[s] = ((u64)wb << 32) | (u64)wb;
    }

    // Fill sh[i] = kx[L0-128+i] for i in [0, N2); zeros where global pos < 0.
    {
        const long base0 = row0 + L0 - HL_;    // 4-aligned (L0 % 2048 == 0)
        const long base1 = row1 + L0 - HL_;
        const float4* x0 = (const float4*)(x + base0);
        const float4* k0 = (const float4*)(k + base0);
        const float4* x1 = (const float4*)(x + base1);
        const float4* k1 = (const float4*)(k + base1);
        const int vzero = (L0 == 0) ? (HL_ / 4) : 0;   // first 32 float4 are pad
        for (int v = tid; v < NV4; v += THREADS) {
            float4 xa, ka, xb, kb;
            if (v < vzero) {
                xa = ka = xb = kb = make_float4(0.f, 0.f, 0.f, 0.f);
            } else {
                xa = x0[v]; ka = k0[v];
                xb = x1[v]; kb = k1[v];
            }
            float a0[4] = {ka.x * xa.x, ka.y * xa.y, ka.z * xa.z, ka.w * xa.w};
            float a1[4] = {kb.x * xb.x, kb.y * xb.y, kb.z * xb.z, kb.w * xb.w};
            #pragma unroll
            for (int j = 0; j < 4; j++)
                sh[padidx(v * 4 + j)] =
                    ((u64)__float_as_uint(a1[j]) << 32) | (u64)__float_as_uint(a0[j]);
        }
    }
    __syncthreads();

    const int l0 = tid * TPT;   // local output offset within tile

    u64 acc[TPT];
    #pragma unroll
    for (int t = 0; t < TPT; t++) acc[t] = 0ULL;

    #pragma unroll 1
    for (int c = 0; c < HL_ / U; c++) {
        // Taps s = U*c+u; input index i = l0 + t + HL - s.
        const int wbase = l0 + HL_ - U * c - (U - 1);
        u64 win[TPT + U - 1];
        #pragma unroll
        for (int j = 0; j < TPT + U - 1; j++) win[j] = sh[padidx(wbase + j)];
        #pragma unroll
        for (int u = 0; u < U; u++) {
            const u64 wv = w2[U * c + u];   // uniform across warp -> broadcast
            #pragma unroll
            for (int t = 0; t < TPT; t++)
                ffma2(acc[t], win[(U - 1 - u) + t], wv);
        }
    }

    // Epilogue: gate by q, float4 stores for both channels.
    {
        const float4* q0 = (const float4*)(q + row0 + L0 + l0);
        const float4* q1 = (const float4*)(q + row1 + L0 + l0);
        float4* o0 = (float4*)(out + row0 + L0 + l0);
        float4* o1 = (float4*)(out + row1 + L0 + l0);
        #pragma unroll
        for (int t4 = 0; t4 < TPT / 4; t4++) {
            float4 qa = q0[t4], qb = q1[t4];
            float4 ra, rb;
            float* pa = &ra.x; float* pb = &rb.x;
            const float* pqa = &qa.x; const float* pqb = &qb.x;
            #pragma unroll
            for (int j = 0; j < 4; j++) {
                u64 a = acc[t4 * 4 + j];
                pa[j] = pqa[j] * __uint_as_float((unsigned)(a & 0xffffffffULL));
                pb[j] = pqb[j] * __uint_as_float((unsigned)(a >> 32));
            }
            o0[t4] = ra;
            o1[t4] = rb;
        }
    }
}

extern "C" void kernel_launch(void* const* d_in, const int* in_sizes, int n_in,
                              void* d_out, int out_size) {
    // metadata order: x, k, q, h  (all float32); output float32 (B,D,L)
    const float* x = (const float*)d_in[0];
    const float* k = (const float*)d_in[1];
    const float* q = (const float*)d_in[2];
    const float* h = (const float*)d_in[3];
    float* out = (float*)d_out;

    dim3 grid(L_ / LT_, D_ / 2, B_);   // 2 x 2048 x 2 = 8192 blocks
    hyena_se_kernel<<<grid, THREADS>>>(x, k, q, h, out);
}

// round 5
// speedup vs baseline: 1.1403x; 1.1403x over previous
#include <cuda_runtime.h>
#include <cstdint>

// HyenaSE gated causal depthwise conv, bdl layout.
// y[b,d,l] = q * sum_{s=0}^{127} (k*x)[b,d,l-s] * h[d%256][127-s]
//
// R5: R4 profile showed LDS-wavefront-bound (L1=88.7%, fma=49.6%). This
// version slides the input window through registers across tap-chunks
// (full unroll -> register renaming): 8 new LDS.64 per chunk instead of 15,
// and weights via 4x LDS.128 broadcast (1 wavefront each) instead of 8x
// LDS.64. Per chunk per block: ~160 smem wavefronts vs 256 FFMA2-issue
// cycles -> FMA-bound.
// Layout as R4: L tiled 2048/block (halo 128), channel pair (d, d+2048)
// shares filter group, kx interleaved float2 in padded smem, mainloop is
// packed fma.rn.f32x2.

typedef unsigned long long u64;

#define B_  2
#define D_  4096
#define L_  4096
#define G_  256
#define HL_ 128
#define LT_ 2048                            // L tile per block

static constexpr int THREADS = 256;
static constexpr int TPT = 8;               // outputs per thread (LT_/THREADS)
static constexpr int U   = 8;               // taps per chunk
static constexpr int NC  = HL_ / U;         // 16 chunks
static constexpr int W   = TPT + U - 1;     // 15-wide register window
static constexpr int N2  = LT_ + HL_;       // 2176 float2 (128 halo + 2048)
static constexpr int NV4 = N2 / 4;          // 544 float4 rows per stream
__device__ __forceinline__ int padidx(int r) { return r + (r >> 4); }
static constexpr int NPAD = N2 + ((N2 - 1) >> 4) + 1;  // 2312

__device__ __forceinline__ void ffma2(u64& acc, u64 a, u64 b) {
    asm("fma.rn.f32x2 %0, %1, %2, %0;" : "+l"(acc) : "l"(a), "l"(b));
}

__global__ void __launch_bounds__(THREADS, 4)
hyena_se_kernel(const float* __restrict__ x, const float* __restrict__ k,
                const float* __restrict__ q, const float* __restrict__ h,
                float* __restrict__ out)
{
    __shared__ u64 sh[NPAD];                     // interleaved kx pairs, padded
    __shared__ __align__(16) u64 w2[HL_];        // reversed filter {w,w}

    const int tid = threadIdx.x;
    const int L0  = blockIdx.x * LT_;            // tile start along L
    const int dp  = blockIdx.y;                  // channel in [0,2048)
    const int b   = blockIdx.z;
    const long row0 = (long)(b * D_ + dp) * L_;
    const long row1 = (long)(b * D_ + dp + 2048) * L_;
    const int g = dp & (G_ - 1);

    // Reversed filter: wrev[s] = h[g][HL-1-s], packed {w,w}
    for (int s = tid; s < HL_; s += THREADS) {
        unsigned wb = __float_as_uint(h[g * HL_ + (HL_ - 1 - s)]);
        w2[s] = ((u64)wb << 32) | (u64)wb;
    }

    // Fill sh[i] = kx[L0-128+i] for i in [0, N2); zeros where global pos < 0.
    {
        const long base0 = row0 + L0 - HL_;      // 4-aligned (L0 % 2048 == 0)
        const long base1 = row1 + L0 - HL_;
        const float4* x0 = (const float4*)(x + base0);
        const float4* k0 = (const float4*)(k + base0);
        const float4* x1 = (const float4*)(x + base1);
        const float4* k1 = (const float4*)(k + base1);
        const int vzero = (L0 == 0) ? (HL_ / 4) : 0;  // first 32 float4 = pad
        for (int v = tid; v < NV4; v += THREADS) {
            float4 xa, ka, xb, kb;
            if (v < vzero) {
                xa = ka = xb = kb = make_float4(0.f, 0.f, 0.f, 0.f);
            } else {
                xa = x0[v]; ka = k0[v];
                xb = x1[v]; kb = k1[v];
            }
            float a0[4] = {ka.x * xa.x, ka.y * xa.y, ka.z * xa.z, ka.w * xa.w};
            float a1[4] = {kb.x * xb.x, kb.y * xb.y, kb.z * xb.z, kb.w * xb.w};
            #pragma unroll
            for (int j = 0; j < 4; j++)
                sh[padidx(v * 4 + j)] =
                    ((u64)__float_as_uint(a1[j]) << 32) | (u64)__float_as_uint(a0[j]);
        }
    }
    __syncthreads();

    const int l0 = tid * TPT;   // local output offset within tile

    u64 acc[TPT];
    #pragma unroll
    for (int t = 0; t < TPT; t++) acc[t] = 0ULL;

    // Sliding register window: win[j] = sh[wbase + j], wbase = l0+HL-7-8c.
    u64 win[W];
    {
        const int wb0 = l0 + HL_ - (U - 1);      // chunk 0 base
        #pragma unroll
        for (int j = 0; j < W; j++) win[j] = sh[padidx(wb0 + j)];
    }

    #pragma unroll
    for (int c = 0; c < NC; c++) {
        // 8 chunk weights via 4 broadcast LDS.128 (1 wavefront each).
        const ulonglong2* wp = (const ulonglong2*)(w2 + U * c);
        ulonglong2 wv[U / 2];
        #pragma unroll
        for (int p = 0; p < U / 2; p++) wv[p] = wp[p];

        #pragma unroll
        for (int u = 0; u < U; u++) {
            const u64 wu = (u & 1) ? wv[u >> 1].y : wv[u >> 1].x;
            #pragma unroll
            for (int t = 0; t < TPT; t++)
                ffma2(acc[t], win[(U - 1 - u) + t], wu);
        }

        // Slide: new wbase = old - 8; reuse old win[0..6] as new win[8..14],
        // load 8 fresh values. Full unroll -> pure register renaming.
        if (c + 1 < NC) {
            #pragma unroll
            for (int j = W - 1; j >= U; j--) win[j] = win[j - U];
            const int wbn = l0 + HL_ - (U - 1) - U * (c + 1);
            #pragma unroll
            for (int j = 0; j < U; j++) win[j] = sh[padidx(wbn + j)];
        }
    }

    // Epilogue: gate by q, float4 stores for both channels.
    {
        const float4* q0 = (const float4*)(q + row0 + L0 + l0);
        const float4* q1 = (const float4*)(q + row1 + L0 + l0);
        float4* o0 = (float4*)(out + row0 + L0 + l0);
        float4* o1 = (float4*)(out + row1 + L0 + l0);
        #pragma unroll
        for (int t4 = 0; t4 < TPT / 4; t4++) {
            float4 qa = q0[t4], qb = q1[t4];
            float4 ra, rb;
            float* pa = &ra.x; float* pb = &rb.x;
            const float* pqa = &qa.x; const float* pqb = &qb.x;
            #pragma unroll
            for (int j = 0; j < 4; j++) {
                u64 a = acc[t4 * 4 + j];
                pa[j] = pqa[j] * __uint_as_float((unsigned)(a & 0xffffffffULL));
                pb[j] = pqb[j] * __uint_as_float((unsigned)(a >> 32));
            }
            o0[t4] = ra;
            o1[t4] = rb;
        }
    }
}

extern "C" void kernel_launch(void* const* d_in, const int* in_sizes, int n_in,
                              void* d_out, int out_size) {
    // metadata order: x, k, q, h  (all float32); output float32 (B,D,L)
    const float* x = (const float*)d_in[0];
    const float* k = (const float*)d_in[1];
    const float* q = (const float*)d_in[2];
    const float* h = (const float*)d_in[3];
    float* out = (float*)d_out;

    dim3 grid(L_ / LT_, D_ / 2, B_);   // 2 x 2048 x 2 = 8192 blocks
    hyena_se_kernel<<<grid, THREADS>>>(x, k, q, h, out);
}

// round 6
// speedup vs baseline: 1.2242x; 1.0736x over previous
#include <cuda_runtime.h>
#include <cstdint>

// HyenaSE gated causal depthwise conv, bdl layout.
// y[b,d,l] = q * sum_{s=0}^{127} (k*x)[b,d,l-s] * h[d%256][127-s]
//
// R6: R5 showed chip-wide phase serialization (dur == traffic/achieved-BW,
// fma=54%, issue=48%). Now each block handles BOTH 2048-tiles of its channel
// pair with a cp.async software pipeline: stage tile B's raw x,k while the
// FMA mainloop runs on tile A. Raw data staged via cp.async.cg (no regs),
// converted (product + channel-interleave) into the padded u64 conv buffer.
// Tile B halo comes from tile A's buffer tail (no gmem reload); tile A halo
// is causal zeros. Mainloop: sliding register window + packed fma.rn.f32x2
// (R5 core). Dynamic smem 51KB, 4 blocks/SM.

typedef unsigned long long u64;

#define B_  2
#define D_  4096
#define L_  4096
#define G_  256
#define HL_ 128
#define LT_ 2048                             // L tile

static constexpr int THREADS = 256;
static constexpr int TPT = 8;                // outputs per thread
static constexpr int U   = 8;                // taps per chunk
static constexpr int NC  = HL_ / U;          // 16 chunks
static constexpr int W   = TPT + U - 1;      // 15-wide register window
static constexpr int N2  = LT_ + HL_;        // 2176 conv-buffer entries
__device__ __forceinline__ int padidx(int r) { return r + (r >> 4); }
static constexpr int NPAD = N2 + ((N2 - 1) >> 4) + 1;   // 2312

// Dynamic smem layout (bytes):
//   [0,1024)        u64  w2[128]       reversed filter {w,w}
//   [1024,33792)    float stg[4][2048] raw x0,k0,x1,k1 staging (cp.async)
//   [33792,52288)   u64  buf[NPAD]     interleaved kx products, padded
static constexpr int SMEM_W2  = 0;
static constexpr int SMEM_STG = 1024;
static constexpr int SMEM_BUF = SMEM_STG + 4 * LT_ * 4;
static constexpr int SMEM_TOTAL = SMEM_BUF + NPAD * 8;   // 52288

__device__ __forceinline__ void ffma2(u64& acc, u64 a, u64 b) {
    asm("fma.rn.f32x2 %0, %1, %2, %0;" : "+l"(acc) : "l"(a), "l"(b));
}
__device__ __forceinline__ void cp16(unsigned daddr, const void* g) {
    asm volatile("cp.async.cg.shared.global [%0], [%1], 16;"
                 :: "r"(daddr), "l"(g));
}

__global__ void __launch_bounds__(THREADS, 4)
hyena_se_kernel(const float* __restrict__ x, const float* __restrict__ k,
                const float* __restrict__ q, const float* __restrict__ h,
                float* __restrict__ out)
{
    extern __shared__ __align__(16) char dsm[];
    u64*   w2  = (u64*)(dsm + SMEM_W2);
    float* stg = (float*)(dsm + SMEM_STG);
    u64*   buf = (u64*)(dsm + SMEM_BUF);
    const unsigned stg_s = (unsigned)__cvta_generic_to_shared(stg);

    const int tid = threadIdx.x;
    const int dp  = blockIdx.x;                 // channel in [0,2048)
    const int b   = blockIdx.y;
    const long row0 = (long)(b * D_ + dp) * L_;
    const long row1 = (long)(b * D_ + dp + 2048) * L_;
    const int g = dp & (G_ - 1);

    // Reversed filter: w2[s] = {h[g][HL-1-s], h[g][HL-1-s]}
    for (int s = tid; s < HL_; s += THREADS) {
        unsigned wb = __float_as_uint(h[g * HL_ + (HL_ - 1 - s)]);
        w2[s] = ((u64)wb << 32) | (u64)wb;
    }

    // Stage tile 0 raw x,k (4 arrays x 2048 floats) via cp.async.
    const float* gsrc[4] = { x + row0, k + row0, x + row1, k + row1 };
    {
        #pragma unroll
        for (int a = 0; a < 4; a++) {
            #pragma unroll
            for (int it = 0; it < LT_ / 4 / THREADS; it++) {   // 2 iters
                int v = it * THREADS + tid;                    // float4 idx
                cp16(stg_s + (unsigned)(a * LT_ + v * 4) * 4,
                     gsrc[a] + (size_t)v * 4);
            }
        }
        asm volatile("cp.async.commit_group;");
    }

    #pragma unroll 1
    for (int tIdx = 0; tIdx < 2; tIdx++) {
        const int tileL = tIdx * LT_;

        asm volatile("cp.async.wait_group 0;");
        __syncthreads();          // staged data + (tIdx=1) prior conv done

        if (tIdx == 0) {
            if (tid < HL_) buf[padidx(tid)] = 0ULL;            // causal pad
        } else {
            // Halo = last 128 positions of tile 0 = buf[2048..2176)
            if (tid < HL_) buf[padidx(tid)] = buf[padidx(LT_ + tid)];
            __syncthreads();      // copy reads tail before products overwrite
        }

        // Convert: buf[128+p] = {k0*x0, k1*x1}[p], p strided by THREADS so
        // STS.64 is lane-consecutive (2-way inherent conflict only).
        {
            const float* xs0 = stg;
            const float* ks0 = stg + LT_;
            const float* xs1 = stg + 2 * LT_;
            const float* ks1 = stg + 3 * LT_;
            #pragma unroll
            for (int it = 0; it < LT_ / THREADS; it++) {       // 8 iters
                int p = it * THREADS + tid;
                float a0 = ks0[p] * xs0[p];
                float a1 = ks1[p] * xs1[p];
                buf[padidx(HL_ + p)] =
                    ((u64)__float_as_uint(a1) << 32) | (u64)__float_as_uint(a0);
            }
        }
        __syncthreads();

        // Stage tile 1 while tile 0's mainloop runs (the overlap).
        if (tIdx == 0) {
            #pragma unroll
            for (int a = 0; a < 4; a++) {
                #pragma unroll
                for (int it = 0; it < LT_ / 4 / THREADS; it++) {
                    int v = it * THREADS + tid;
                    cp16(stg_s + (unsigned)(a * LT_ + v * 4) * 4,
                         gsrc[a] + (size_t)(LT_ + v * 4));
                }
            }
            asm volatile("cp.async.commit_group;");
        }

        // ---- mainloop: sliding register window + FFMA2 ----
        const int l0 = tid * TPT;

        u64 acc[TPT];
        #pragma unroll
        for (int t = 0; t < TPT; t++) acc[t] = 0ULL;

        u64 win[W];
        {
            const int wb0 = l0 + HL_ - (U - 1);
            #pragma unroll
            for (int j = 0; j < W; j++) win[j] = buf[padidx(wb0 + j)];
        }

        #pragma unroll
        for (int c = 0; c < NC; c++) {
            const ulonglong2* wp = (const ulonglong2*)(w2 + U * c);
            ulonglong2 wv[U / 2];
            #pragma unroll
            for (int p = 0; p < U / 2; p++) wv[p] = wp[p];

            #pragma unroll
            for (int u = 0; u < U; u++) {
                const u64 wu = (u & 1) ? wv[u >> 1].y : wv[u >> 1].x;
                #pragma unroll
                for (int t = 0; t < TPT; t++)
                    ffma2(acc[t], win[(U - 1 - u) + t], wu);
            }
            if (c + 1 < NC) {
                #pragma unroll
                for (int j = W - 1; j >= U; j--) win[j] = win[j - U];
                const int wbn = l0 + HL_ - (U - 1) - U * (c + 1);
                #pragma unroll
                for (int j = 0; j < U; j++) win[j] = buf[padidx(wbn + j)];
            }
        }

        // ---- epilogue: gate by q, float4 stores ----
        {
            const float4* q0 = (const float4*)(q + row0 + tileL + l0);
            const float4* q1 = (const float4*)(q + row1 + tileL + l0);
            float4* o0 = (float4*)(out + row0 + tileL + l0);
            float4* o1 = (float4*)(out + row1 + tileL + l0);
            #pragma unroll
            for (int t4 = 0; t4 < TPT / 4; t4++) {
                float4 qa = q0[t4], qb = q1[t4];
                float4 ra, rb;
                float* pa = &ra.x; float* pb = &rb.x;
                const float* pqa = &qa.x; const float* pqb = &qb.x;
                #pragma unroll
                for (int j = 0; j < 4; j++) {
                    u64 a = acc[t4 * 4 + j];
                    pa[j] = pqa[j] * __uint_as_float((unsigned)(a & 0xffffffffULL));
                    pb[j] = pqb[j] * __uint_as_float((unsigned)(a >> 32));
                }
                o0[t4] = ra;
                o1[t4] = rb;
            }
        }
    }
}

extern "C" void kernel_launch(void* const* d_in, const int* in_sizes, int n_in,
                              void* d_out, int out_size) {
    // metadata order: x, k, q, h  (all float32); output float32 (B,D,L)
    const float* x = (const float*)d_in[0];
    const float* k = (const float*)d_in[1];
    const float* q = (const float*)d_in[2];
    const float* h = (const float*)d_in[3];
    float* out = (float*)d_out;

    cudaFuncSetAttribute(hyena_se_kernel,
                         cudaFuncAttributeMaxDynamicSharedMemorySize,
                         SMEM_TOTAL);
    dim3 grid(D_ / 2, B_);   // 2048 x 2 blocks, each does both L tiles
    hyena_se_kernel<<<grid, THREADS, SMEM_TOTAL>>>(x, k, q, h, out);
}

// round 7
// speedup vs baseline: 1.3268x; 1.0838x over previous
#include <cuda_runtime.h>
#include <cstdint>

// HyenaSE gated causal depthwise conv, bdl layout.
// y[b,d,l] = q * sum_{s=0}^{127} (k*x)[b,d,l-s] * h[d%256][127-s]
//
// R7: R6 was smem-wavefront-limited (L1=74%, fma=58%): LDS.64 window loads
// at 64B lane stride cost ~2x minimum wavefronts. Now the conv buffer pads
// 2 u64 per 16 (idx = r + 2*(r>>4)): even indices are 16B-aligned, pairs
// never straddle a pad, and the lane->bank-quad map is conflict-free, so
// window loads become 4-wavefront LDS.128. Per chunk-warp: 4 LDS.128 +
// 4 broadcast weight loads vs 64 FFMA2 -> FMA-bound with margin.
// Retains R6's cp.async two-tile pipeline (stage tile B's raw x,k during
// tile A's FMA burst; tile B halo recycled from tile A's buffer tail).

typedef unsigned long long u64;

#define B_  2
#define D_  4096
#define L_  4096
#define G_  256
#define HL_ 128
#define LT_ 2048                             // L tile

static constexpr int THREADS = 256;
static constexpr int TPT = 8;                // outputs per thread
static constexpr int U   = 8;                // taps per chunk
static constexpr int NC  = HL_ / U;          // 16 chunks
static constexpr int N2  = LT_ + HL_;        // 2176 conv-buffer entries
// Pad 2 u64 per 16: keeps 16B alignment of even indices; conflict-free quads.
__device__ __forceinline__ int padidx(int r) { return r + 2 * (r >> 4); }
static constexpr int NPAD = (N2 - 1) + 2 * ((N2 - 1) >> 4) + 1;   // 2446

// Dynamic smem layout (bytes):
//   [0,1024)        u64  w2[128]       reversed filter {w,w}
//   [1024,33792)    float stg[4][2048] raw x0,k0,x1,k1 staging (cp.async)
//   [33792,53360)   u64  buf[NPAD]     interleaved kx products, padded
static constexpr int SMEM_W2  = 0;
static constexpr int SMEM_STG = 1024;
static constexpr int SMEM_BUF = SMEM_STG + 4 * LT_ * 4;
static constexpr int SMEM_TOTAL = SMEM_BUF + NPAD * 8;   // 53360

__device__ __forceinline__ void ffma2(u64& acc, u64 a, u64 b) {
    asm("fma.rn.f32x2 %0, %1, %2, %0;" : "+l"(acc) : "l"(a), "l"(b));
}
__device__ __forceinline__ void cp16(unsigned daddr, const void* g) {
    asm volatile("cp.async.cg.shared.global [%0], [%1], 16;"
                 :: "r"(daddr), "l"(g));
}

__global__ void __launch_bounds__(THREADS, 4)
hyena_se_kernel(const float* __restrict__ x, const float* __restrict__ k,
                const float* __restrict__ q, const float* __restrict__ h,
                float* __restrict__ out)
{
    extern __shared__ __align__(16) char dsm[];
    u64*   w2  = (u64*)(dsm + SMEM_W2);
    float* stg = (float*)(dsm + SMEM_STG);
    u64*   buf = (u64*)(dsm + SMEM_BUF);
    const unsigned stg_s = (unsigned)__cvta_generic_to_shared(stg);

    const int tid = threadIdx.x;
    const int dp  = blockIdx.x;                 // channel in [0,2048)
    const int b   = blockIdx.y;
    const long row0 = (long)(b * D_ + dp) * L_;
    const long row1 = (long)(b * D_ + dp + 2048) * L_;
    const int g = dp & (G_ - 1);

    // Reversed filter: w2[s] = {h[g][HL-1-s], h[g][HL-1-s]}
    for (int s = tid; s < HL_; s += THREADS) {
        unsigned wb = __float_as_uint(h[g * HL_ + (HL_ - 1 - s)]);
        w2[s] = ((u64)wb << 32) | (u64)wb;
    }

    // Stage tile 0 raw x,k (4 arrays x 2048 floats) via cp.async.
    const float* gsrc[4] = { x + row0, k + row0, x + row1, k + row1 };
    {
        #pragma unroll
        for (int a = 0; a < 4; a++) {
            #pragma unroll
            for (int it = 0; it < LT_ / 4 / THREADS; it++) {   // 2 iters
                int v = it * THREADS + tid;                    // float4 idx
                cp16(stg_s + (unsigned)(a * LT_ + v * 4) * 4,
                     gsrc[a] + (size_t)v * 4);
            }
        }
        asm volatile("cp.async.commit_group;");
    }

    #pragma unroll 1
    for (int tIdx = 0; tIdx < 2; tIdx++) {
        const int tileL = tIdx * LT_;

        asm volatile("cp.async.wait_group 0;");
        __syncthreads();          // staged data + (tIdx=1) prior conv done

        if (tIdx == 0) {
            if (tid < HL_) buf[padidx(tid)] = 0ULL;            // causal pad
        } else {
            // Halo = last 128 positions of tile 0 = buf[2048..2176)
            if (tid < HL_) buf[padidx(tid)] = buf[padidx(LT_ + tid)];
            __syncthreads();      // copy reads tail before products overwrite
        }

        // Convert: buf[128+p] = {k0*x0, k1*x1}[p], lane-consecutive STS.64.
        {
            const float* xs0 = stg;
            const float* ks0 = stg + LT_;
            const float* xs1 = stg + 2 * LT_;
            const float* ks1 = stg + 3 * LT_;
            #pragma unroll
            for (int it = 0; it < LT_ / THREADS; it++) {       // 8 iters
                int p = it * THREADS + tid;
                float a0 = ks0[p] * xs0[p];
                float a1 = ks1[p] * xs1[p];
                buf[padidx(HL_ + p)] =
                    ((u64)__float_as_uint(a1) << 32) | (u64)__float_as_uint(a0);
            }
        }
        __syncthreads();

        // Stage tile 1 while tile 0's mainloop runs (the overlap).
        if (tIdx == 0) {
            #pragma unroll
            for (int a = 0; a < 4; a++) {
                #pragma unroll
                for (int it = 0; it < LT_ / 4 / THREADS; it++) {
                    int v = it * THREADS + tid;
                    cp16(stg_s + (unsigned)(a * LT_ + v * 4) * 4,
                         gsrc[a] + (size_t)(LT_ + v * 4));
                }
            }
            asm volatile("cp.async.commit_group;");
        }

        // ---- mainloop: LDS.128 sliding window + FFMA2 ----
        const int l0 = tid * TPT;
        const int wb0 = l0 + HL_ - (U - 1);       // 8*tid + 121 (odd)

        u64 acc[TPT];
        #pragma unroll
        for (int t = 0; t < TPT; t++) acc[t] = 0ULL;

        // Invariant at chunk c: win[j] = buf value at (wb0 - 8c - 1 + j),
        // j in [0,16); FMA uses positions (wb0-8c)+m via win[m+1].
        u64 win[16];
        #pragma unroll
        for (int p = 0; p < 8; p++) {             // initial 8 LDS.128
            ulonglong2 v = *(const ulonglong2*)&buf[padidx(wb0 - 1 + 2 * p)];
            win[2 * p]     = v.x;
            win[2 * p + 1] = v.y;
        }

        #pragma unroll
        for (int c = 0; c < NC; c++) {
            #pragma unroll
            for (int pw = 0; pw < U / 2; pw++) {
                // 2 weights per broadcast LDS.128
                ulonglong2 wv = ((const ulonglong2*)(w2 + U * c))[pw];
                #pragma unroll
                for (int h2 = 0; h2 < 2; h2++) {
                    const int u = 2 * pw + h2;
                    const u64 wu = h2 ? wv.y : wv.x;
                    #pragma unroll
                    for (int t = 0; t < TPT; t++)
                        ffma2(acc[t], win[(U - 1 - u) + t + 1], wu);
                }
            }
            // Slide: keep old win[0..7] as new win[8..15]; load 4 LDS.128
            // covering [wbc-9, wbc-2] (even-aligned; win[0] is the spare).
            if (c + 1 < NC) {
                #pragma unroll
                for (int j = 15; j >= 8; j--) win[j] = win[j - 8];
                const int rb = wb0 - 8 * c - 9;   // even
                #pragma unroll
                for (int p = 0; p < 4; p++) {
                    ulonglong2 v = *(const ulonglong2*)&buf[padidx(rb + 2 * p)];
                    win[2 * p]     = v.x;
                    win[2 * p + 1] = v.y;
                }
            }
        }

        // ---- epilogue: gate by q, float4 stores ----
        {
            const float4* q0 = (const float4*)(q + row0 + tileL + l0);
            const float4* q1 = (const float4*)(q + row1 + tileL + l0);
            float4* o0 = (float4*)(out + row0 + tileL + l0);
            float4* o1 = (float4*)(out + row1 + tileL + l0);
            #pragma unroll
            for (int t4 = 0; t4 < TPT / 4; t4++) {
                float4 qa = q0[t4], qb = q1[t4];
                float4 ra, rb;
                float* pa = &ra.x; float* pb = &rb.x;
                const float* pqa = &qa.x; const float* pqb = &qb.x;
                #pragma unroll
                for (int j = 0; j < 4; j++) {
                    u64 a = acc[t4 * 4 + j];
                    pa[j] = pqa[j] * __uint_as_float((unsigned)(a & 0xffffffffULL));
                    pb[j] = pqb[j] * __uint_as_float((unsigned)(a >> 32));
                }
                o0[t4] = ra;
                o1[t4] = rb;
            }
        }
    }
}

extern "C" void kernel_launch(void* const* d_in, const int* in_sizes, int n_in,
                              void* d_out, int out_size) {
    // metadata order: x, k, q, h  (all float32); output float32 (B,D,L)
    const float* x = (const float*)d_in[0];
    const float* k = (const float*)d_in[1];
    const float* q = (const float*)d_in[2];
    const float* h = (const float*)d_in[3];
    float* out = (float*)d_out;

    cudaFuncSetAttribute(hyena_se_kernel,
                         cudaFuncAttributeMaxDynamicSharedMemorySize,
                         SMEM_TOTAL);
    dim3 grid(D_ / 2, B_);   // 2048 x 2 blocks, each does both L tiles
    hyena_se_kernel<<<grid, THREADS, SMEM_TOTAL>>>(x, k, q, h, out);
}